// round 1
// baseline (speedup 1.0000x reference)
#include <cuda_runtime.h>
#include <cstddef>

// Problem constants: B=16, T=960, D=1024, W=10
#define DDIM   1024
#define WWIN   10
#define MTOT   15360          // B*T
#define KCONV  3072           // 3 * D

#define BM 128
#define BN 128
#define BK 8

// Scratch (device globals: allocation-free per harness rules)
__device__ float g_cnn[(size_t)MTOT * DDIM];     // ~63 MB
__device__ float g_Wt[(size_t)KCONV * DDIM];     // conv_w transposed to [k=s*1024+c][d]
__device__ float g_Gt[(size_t)DDIM * DDIM];      // gate_w transposed to [d][e]

// ---------------------------------------------------------------------------
// Wt[(s*1024 + c)*1024 + d] = conv_w[d*3072 + c*3 + s]
// Output-coalesced; conv_w (12.6MB) is L2-resident so scattered reads are cheap.
// ---------------------------------------------------------------------------
__global__ void k_transpose_convw(const float* __restrict__ w) {
    int idx = blockIdx.x * blockDim.x + threadIdx.x;   // over KCONV*DDIM (exact)
    int d    = idx & (DDIM - 1);
    int rest = idx >> 10;            // s*1024 + c
    int c    = rest & (DDIM - 1);
    int s    = rest >> 10;
    g_Wt[idx] = w[(size_t)d * (DDIM * 3) + c * 3 + s];
}

// Gt[d*1024 + e] = gate_w[e*1024 + d]
__global__ void k_transpose_gatew(const float* __restrict__ gw) {
    int idx = blockIdx.x * blockDim.x + threadIdx.x;   // over DDIM*DDIM (exact)
    int e = idx & (DDIM - 1);
    int d = idx >> 10;
    g_Gt[idx] = gw[(size_t)e * DDIM + d];
}

// ---------------------------------------------------------------------------
// Conv GEMM: cnn[m, n] = sum_{k<3072} A[m,k] * Wt[k, n] + conv_b[n]
//   A[m, k] = x[(m + s - 1)*D + c]  if (m%10 + s - 1) in [0,10), else 0
//   with s = k/1024, c = k%1024.  (Window-edge zero padding folded in.)
// 128x128x8 tiling, 256 threads, 8x8 per-thread micro-tile (2x2 float4 frags).
// ---------------------------------------------------------------------------
__global__ __launch_bounds__(256, 2)
void k_conv_gemm(const float* __restrict__ x, const float* __restrict__ cb) {
    __shared__ __align__(16) float As[BK][BM];
    __shared__ __align__(16) float Bs[BK][BN];

    const int tid = threadIdx.x;
    const int tx = tid & 15;          // 0..15  (N direction)
    const int ty = tid >> 4;          // 0..15  (M direction)
    const int m0 = blockIdx.y * BM;
    const int n0 = blockIdx.x * BN;

    // A loader: 128 rows x 8 k, two float4 per row
    const int a_row  = tid >> 1;            // 0..127
    const int a_quad = (tid & 1) * 4;       // 0 or 4
    // B loader: 8 k-rows x 128 n, one float4 each
    const int b_row = tid >> 5;             // 0..7
    const int b_col = (tid & 31) * 4;       // 0..124

    const int m  = m0 + a_row;
    const int ww = m % WWIN;                // window offset of this row

    float acc[8][8];
#pragma unroll
    for (int i = 0; i < 8; ++i)
#pragma unroll
        for (int j = 0; j < 8; ++j) acc[i][j] = 0.f;

    for (int kb = 0; kb < KCONV; kb += BK) {
        const int s  = kb >> 10;            // 0,1,2 (constant within k-block)
        const int dt = s - 1;
        const int c  = (kb & (DDIM - 1)) + a_quad;

        float4 av = make_float4(0.f, 0.f, 0.f, 0.f);
        const int wv = ww + dt;
        if (wv >= 0 && wv < WWIN)
            av = *reinterpret_cast<const float4*>(x + (size_t)(m + dt) * DDIM + c);
        As[a_quad + 0][a_row] = av.x;
        As[a_quad + 1][a_row] = av.y;
        As[a_quad + 2][a_row] = av.z;
        As[a_quad + 3][a_row] = av.w;

        *reinterpret_cast<float4*>(&Bs[b_row][b_col]) =
            *reinterpret_cast<const float4*>(g_Wt + (size_t)(kb + b_row) * DDIM + n0 + b_col);

        __syncthreads();

#pragma unroll
        for (int kk = 0; kk < BK; ++kk) {
            const float4 a0 = *reinterpret_cast<const float4*>(&As[kk][ty * 4]);
            const float4 a1 = *reinterpret_cast<const float4*>(&As[kk][64 + ty * 4]);
            const float4 b0 = *reinterpret_cast<const float4*>(&Bs[kk][tx * 4]);
            const float4 b1 = *reinterpret_cast<const float4*>(&Bs[kk][64 + tx * 4]);
            const float ar[8] = {a0.x, a0.y, a0.z, a0.w, a1.x, a1.y, a1.z, a1.w};
            const float br[8] = {b0.x, b0.y, b0.z, b0.w, b1.x, b1.y, b1.z, b1.w};
#pragma unroll
            for (int i = 0; i < 8; ++i)
#pragma unroll
                for (int j = 0; j < 8; ++j)
                    acc[i][j] = fmaf(ar[i], br[j], acc[i][j]);
        }
        __syncthreads();
    }

    // Epilogue: add bias, store cnn
#pragma unroll
    for (int ih = 0; ih < 2; ++ih) {
#pragma unroll
        for (int i = 0; i < 4; ++i) {
            const int gm = m0 + ih * 64 + ty * 4 + i;
#pragma unroll
            for (int jh = 0; jh < 2; ++jh) {
                const int gn = n0 + jh * 64 + tx * 4;
                float4 o;
                o.x = acc[ih * 4 + i][jh * 4 + 0] + cb[gn + 0];
                o.y = acc[ih * 4 + i][jh * 4 + 1] + cb[gn + 1];
                o.z = acc[ih * 4 + i][jh * 4 + 2] + cb[gn + 2];
                o.w = acc[ih * 4 + i][jh * 4 + 3] + cb[gn + 3];
                *reinterpret_cast<float4*>(g_cnn + (size_t)gm * DDIM + gn) = o;
            }
        }
    }
}

// ---------------------------------------------------------------------------
// Gate GEMM: v[m, e] = sum_d cnn[m,d] * Gt[d, e] + gate_b[e]
//            out[m, e] = cnn[m, e] * sigmoid(v[m, e])
// ---------------------------------------------------------------------------
__global__ __launch_bounds__(256, 2)
void k_gate_gemm(const float* __restrict__ gb, float* __restrict__ out) {
    __shared__ __align__(16) float As[BK][BM];
    __shared__ __align__(16) float Bs[BK][BN];

    const int tid = threadIdx.x;
    const int tx = tid & 15;
    const int ty = tid >> 4;
    const int m0 = blockIdx.y * BM;
    const int n0 = blockIdx.x * BN;

    const int a_row  = tid >> 1;
    const int a_quad = (tid & 1) * 4;
    const int b_row = tid >> 5;
    const int b_col = (tid & 31) * 4;

    float acc[8][8];
#pragma unroll
    for (int i = 0; i < 8; ++i)
#pragma unroll
        for (int j = 0; j < 8; ++j) acc[i][j] = 0.f;

    for (int kb = 0; kb < DDIM; kb += BK) {
        const float4 av = *reinterpret_cast<const float4*>(
            g_cnn + (size_t)(m0 + a_row) * DDIM + kb + a_quad);
        As[a_quad + 0][a_row] = av.x;
        As[a_quad + 1][a_row] = av.y;
        As[a_quad + 2][a_row] = av.z;
        As[a_quad + 3][a_row] = av.w;

        *reinterpret_cast<float4*>(&Bs[b_row][b_col]) =
            *reinterpret_cast<const float4*>(g_Gt + (size_t)(kb + b_row) * DDIM + n0 + b_col);

        __syncthreads();

#pragma unroll
        for (int kk = 0; kk < BK; ++kk) {
            const float4 a0 = *reinterpret_cast<const float4*>(&As[kk][ty * 4]);
            const float4 a1 = *reinterpret_cast<const float4*>(&As[kk][64 + ty * 4]);
            const float4 b0 = *reinterpret_cast<const float4*>(&Bs[kk][tx * 4]);
            const float4 b1 = *reinterpret_cast<const float4*>(&Bs[kk][64 + tx * 4]);
            const float ar[8] = {a0.x, a0.y, a0.z, a0.w, a1.x, a1.y, a1.z, a1.w};
            const float br[8] = {b0.x, b0.y, b0.z, b0.w, b1.x, b1.y, b1.z, b1.w};
#pragma unroll
            for (int i = 0; i < 8; ++i)
#pragma unroll
                for (int j = 0; j < 8; ++j)
                    acc[i][j] = fmaf(ar[i], br[j], acc[i][j]);
        }
        __syncthreads();
    }

    // Epilogue: sigmoid gate, multiply by cnn at same coords
#pragma unroll
    for (int ih = 0; ih < 2; ++ih) {
#pragma unroll
        for (int i = 0; i < 4; ++i) {
            const int gm = m0 + ih * 64 + ty * 4 + i;
#pragma unroll
            for (int jh = 0; jh < 2; ++jh) {
                const int gn = n0 + jh * 64 + tx * 4;
                const float4 cv = *reinterpret_cast<const float4*>(
                    g_cnn + (size_t)gm * DDIM + gn);
                float v0 = acc[ih * 4 + i][jh * 4 + 0] + gb[gn + 0];
                float v1 = acc[ih * 4 + i][jh * 4 + 1] + gb[gn + 1];
                float v2 = acc[ih * 4 + i][jh * 4 + 2] + gb[gn + 2];
                float v3 = acc[ih * 4 + i][jh * 4 + 3] + gb[gn + 3];
                float4 o;
                o.x = cv.x * (1.f / (1.f + __expf(-v0)));
                o.y = cv.y * (1.f / (1.f + __expf(-v1)));
                o.z = cv.z * (1.f / (1.f + __expf(-v2)));
                o.w = cv.w * (1.f / (1.f + __expf(-v3)));
                *reinterpret_cast<float4*>(out + (size_t)gm * DDIM + gn) = o;
            }
        }
    }
}

// ---------------------------------------------------------------------------
extern "C" void kernel_launch(void* const* d_in, const int* in_sizes, int n_in,
                              void* d_out, int out_size) {
    const float* x      = (const float*)d_in[0];
    const float* conv_w = (const float*)d_in[1];
    const float* conv_b = (const float*)d_in[2];
    const float* gate_w = (const float*)d_in[3];
    const float* gate_b = (const float*)d_in[4];
    float* out = (float*)d_out;

    k_transpose_convw<<<(KCONV * DDIM) / 256, 256>>>(conv_w);
    k_transpose_gatew<<<(DDIM * DDIM) / 256, 256>>>(gate_w);

    dim3 grid(DDIM / BN, MTOT / BM);   // (8, 120)
    k_conv_gemm<<<grid, 256>>>(x, conv_b);
    k_gate_gemm<<<grid, 256>>>(gate_b, out);
}

// round 3
// speedup vs baseline: 2.1461x; 2.1461x over previous
#include <cuda_runtime.h>
#include <cuda_bf16.h>
#include <cstdint>
#include <cstddef>

// Problem: B=16, T=960, D=1024, W=10
#define DDIM  1024
#define WWIN  10
#define MTOT  15360          // B*T
#define KCONV 3072           // 3*D

static constexpr size_t XSZ = (size_t)MTOT * DDIM;
static constexpr size_t WSZ = (size_t)DDIM * KCONV;
static constexpr size_t GSZ = (size_t)DDIM * DDIM;

// Device scratch (allocation-free rules)
__device__ float          g_cnn[XSZ];       // fp32 cnn
__device__ __nv_bfloat16  g_x2[2 * XSZ];    // x   hi|lo, [m][c]
__device__ __nv_bfloat16  g_w2[2 * WSZ];    // conv w hi|lo, [n][k=s*1024+c]
__device__ __nv_bfloat16  g_g2[2 * GSZ];    // gate w hi|lo, [e][d]
__device__ __nv_bfloat16  g_c2[2 * XSZ];    // cnn hi|lo, [m][d]

// ------------------------------------------------------------------ PTX helpers
__device__ __forceinline__ uint32_t smem_u32(const void* p) {
    uint32_t a;
    asm("{ .reg .u64 t; cvta.to.shared.u64 t, %1; cvt.u32.u64 %0, t; }" : "=r"(a) : "l"(p));
    return a;
}
__device__ __forceinline__ void cp16(uint32_t dst, const void* src, uint32_t sz) {
    asm volatile("cp.async.cg.shared.global [%0], [%1], 16, %2;"
                 :: "r"(dst), "l"(src), "r"(sz) : "memory");
}
__device__ __forceinline__ void cp_commit() {
    asm volatile("cp.async.commit_group;" ::: "memory");
}
template <int N>
__device__ __forceinline__ void cp_wait() {
    asm volatile("cp.async.wait_group %0;" :: "n"(N) : "memory");
}
__device__ __forceinline__ void ldsm4(uint32_t* r, uint32_t addr) {
    asm volatile("ldmatrix.sync.aligned.m8n8.x4.shared.b16 {%0,%1,%2,%3}, [%4];"
                 : "=r"(r[0]), "=r"(r[1]), "=r"(r[2]), "=r"(r[3]) : "r"(addr));
}
__device__ __forceinline__ void mma16816(float* d, const uint32_t* a, const uint32_t* b) {
    asm volatile("mma.sync.aligned.m16n8k16.row.col.f32.bf16.bf16.f32 "
                 "{%0,%1,%2,%3}, {%4,%5,%6,%7}, {%8,%9}, {%0,%1,%2,%3};"
                 : "+f"(d[0]), "+f"(d[1]), "+f"(d[2]), "+f"(d[3])
                 : "r"(a[0]), "r"(a[1]), "r"(a[2]), "r"(a[3]), "r"(b[0]), "r"(b[1]));
}
__device__ __forceinline__ uint32_t pack_bf16x2(float a, float b) {
    __nv_bfloat16 ha = __float2bfloat16(a), hb = __float2bfloat16(b);
    return (uint32_t)__bfloat16_as_ushort(ha) | ((uint32_t)__bfloat16_as_ushort(hb) << 16);
}

// ------------------------------------------------------------------ preprocessing
__global__ void k_split_x(const float* __restrict__ x) {
    size_t i = ((size_t)blockIdx.x * 256 + threadIdx.x) * 4;
    float4 v = *reinterpret_cast<const float4*>(x + i);
    float vv[4] = {v.x, v.y, v.z, v.w};
    float hw[4];
#pragma unroll
    for (int j = 0; j < 4; ++j) hw[j] = __bfloat162float(__float2bfloat16(vv[j]));
    uint2 uh, ul;
    uh.x = pack_bf16x2(vv[0], vv[1]); uh.y = pack_bf16x2(vv[2], vv[3]);
    ul.x = pack_bf16x2(vv[0] - hw[0], vv[1] - hw[1]);
    ul.y = pack_bf16x2(vv[2] - hw[2], vv[3] - hw[3]);
    *reinterpret_cast<uint2*>(g_x2 + i)       = uh;
    *reinterpret_cast<uint2*>(g_x2 + XSZ + i) = ul;
}
__global__ void k_split_convw(const float* __restrict__ w) {
    size_t i = (size_t)blockIdx.x * 256 + threadIdx.x;   // over WSZ, layout [n][s*1024+c]
    int n = (int)(i / KCONV);
    int k = (int)(i - (size_t)n * KCONV);
    int s = k >> 10, c = k & (DDIM - 1);
    float v = w[(size_t)n * KCONV + c * 3 + s];
    __nv_bfloat16 h = __float2bfloat16(v);
    g_w2[i]       = h;
    g_w2[WSZ + i] = __float2bfloat16(v - __bfloat162float(h));
}
__global__ void k_split_gatew(const float* __restrict__ gw) {
    size_t i = ((size_t)blockIdx.x * 256 + threadIdx.x) * 4;
    float4 v = *reinterpret_cast<const float4*>(gw + i);
    float vv[4] = {v.x, v.y, v.z, v.w};
    float hw[4];
#pragma unroll
    for (int j = 0; j < 4; ++j) hw[j] = __bfloat162float(__float2bfloat16(vv[j]));
    uint2 uh, ul;
    uh.x = pack_bf16x2(vv[0], vv[1]); uh.y = pack_bf16x2(vv[2], vv[3]);
    ul.x = pack_bf16x2(vv[0] - hw[0], vv[1] - hw[1]);
    ul.y = pack_bf16x2(vv[2] - hw[2], vv[3] - hw[3]);
    *reinterpret_cast<uint2*>(g_g2 + i)       = uh;
    *reinterpret_cast<uint2*>(g_g2 + GSZ + i) = ul;
}

// ------------------------------------------------------------------ main GEMM
// CTA 128x128, BK=64 bf16. smem buffer: [Ah|Al|Bh|Bl] 16KB planes, x2 buffers.
// 8 warps (2 M x 4 N), warp tile 64x32, mma.sync m16n8k16 bf16, 3-pass split fp32.
static constexpr int PL_AH = 0, PL_AL = 16384, PL_BH = 32768, PL_BL = 49152;
static constexpr int BUFSZ = 65536;
static constexpr int SMEM_SZ = 2 * BUFSZ;   // 128 KB

template <int CHUNKS, bool IS_CONV>
__global__ __launch_bounds__(256, 1)
void k_mma(const float* __restrict__ bias, float* __restrict__ out) {
    extern __shared__ char smem[];
    const uint32_t sb = smem_u32(smem);

    const int tid = threadIdx.x;
    const int m0 = blockIdx.y * 128, n0 = blockIdx.x * 128;
    const int lane = tid & 31, w = tid >> 5;
    const int wm = w >> 2, wn = w & 3;          // warp grid 2(M) x 4(N)
    const int li = lane & 7, lg = lane >> 3;

    // ---- loader geometry: thread -> (row r, 4 of 8 16B sub-chunks)
    const int lr = tid >> 1;                    // 0..127
    const int lh = (tid & 1) * 4;               // sub-chunk base (0 or 4)
    const int am = m0 + lr;                     // A global row (pre-shift)
    const int amw = am % WWIN;
    const size_t ALO = XSZ;
    const size_t BLO = IS_CONV ? WSZ : GSZ;

    auto load_chunk = [&](int c, int buf) {
        const uint32_t base = sb + buf * BUFSZ;
        const __nv_bfloat16* Ap;
        const __nv_bfloat16* Bp;
        uint32_t asz = 16;
        if (IS_CONV) {
            const int s = c >> 4, dt = s - 1, kc = (c & 15) << 6;
            const bool valid = ((unsigned)(amw + dt)) < (unsigned)WWIN;
            asz = valid ? 16u : 0u;
            Ap = g_x2 + (size_t)(valid ? (am + dt) : am) * DDIM + kc;
            Bp = g_w2 + (size_t)(n0 + lr) * KCONV + (c << 6);
        } else {
            Ap = g_c2 + (size_t)am * DDIM + (c << 6);
            Bp = g_g2 + (size_t)(n0 + lr) * DDIM + (c << 6);
        }
#pragma unroll
        for (int j = 0; j < 4; ++j) {
            const int cc = lh + j;
            const uint32_t d = base + lr * 128 + ((cc ^ (lr & 7)) * 16);
            cp16(d + PL_AH, Ap + cc * 8, asz);
            cp16(d + PL_AL, Ap + ALO + cc * 8, asz);
            cp16(d + PL_BH, Bp + cc * 8, 16);
            cp16(d + PL_BL, Bp + BLO + cc * 8, 16);
        }
    };

    float acc[4][4][4];
#pragma unroll
    for (int i = 0; i < 4; ++i)
#pragma unroll
        for (int j = 0; j < 4; ++j)
#pragma unroll
            for (int q = 0; q < 4; ++q) acc[i][j][q] = 0.f;

    load_chunk(0, 0);
    cp_commit();

    for (int it = 0; it < CHUNKS; ++it) {
        const int buf = it & 1;
        if (it + 1 < CHUNKS) { load_chunk(it + 1, buf ^ 1); cp_commit(); }
        if (it + 1 < CHUNKS) cp_wait<1>(); else cp_wait<0>();
        __syncthreads();

        const uint32_t bb = sb + buf * BUFSZ;
#pragma unroll
        for (int ks = 0; ks < 4; ++ks) {
            // B fragments: two ldmatrix.x4 per plane cover n32 x k16
            uint32_t Bh[2][4], Bl[2][4];
#pragma unroll
            for (int nt2 = 0; nt2 < 2; ++nt2) {
                const int br = wn * 32 + nt2 * 16 + li + (lg >> 1) * 8;
                const uint32_t cx = (uint32_t)((ks * 2 + (lg & 1)) ^ li);
                const uint32_t ba = bb + br * 128 + cx * 16;
                ldsm4(Bh[nt2], ba + PL_BH);
                ldsm4(Bl[nt2], ba + PL_BL);
            }
#pragma unroll
            for (int mt = 0; mt < 4; ++mt) {
                const int ar = wm * 64 + mt * 16 + li + (lg & 1) * 8;
                const uint32_t cx = (uint32_t)((ks * 2 + (lg >> 1)) ^ li);
                const uint32_t aa = bb + ar * 128 + cx * 16;
                uint32_t Ah[4], Al[4];
                ldsm4(Ah, aa + PL_AH);
                ldsm4(Al, aa + PL_AL);
#pragma unroll
                for (int nt = 0; nt < 4; ++nt) {
                    const uint32_t bh[2] = {Bh[nt >> 1][(nt & 1) * 2], Bh[nt >> 1][(nt & 1) * 2 + 1]};
                    const uint32_t bl[2] = {Bl[nt >> 1][(nt & 1) * 2], Bl[nt >> 1][(nt & 1) * 2 + 1]};
                    mma16816(acc[mt][nt], Ah, bh);
                    mma16816(acc[mt][nt], Ah, bl);
                    mma16816(acc[mt][nt], Al, bh);
                }
            }
        }
        __syncthreads();
    }

    // ---- epilogue (direct from fragments)
#pragma unroll
    for (int mt = 0; mt < 4; ++mt) {
#pragma unroll
        for (int nt = 0; nt < 4; ++nt) {
            const int gn = n0 + wn * 32 + nt * 8 + (lane & 3) * 2;
            const float b0 = bias[gn], b1 = bias[gn + 1];
#pragma unroll
            for (int hh = 0; hh < 2; ++hh) {
                const int gm = m0 + wm * 64 + mt * 16 + (lane >> 2) + hh * 8;
                float v0 = acc[mt][nt][hh * 2 + 0] + b0;
                float v1 = acc[mt][nt][hh * 2 + 1] + b1;
                const size_t off = (size_t)gm * DDIM + gn;
                if (IS_CONV) {
                    *reinterpret_cast<float2*>(g_cnn + off) = make_float2(v0, v1);
                    const float h0 = __bfloat162float(__float2bfloat16(v0));
                    const float h1 = __bfloat162float(__float2bfloat16(v1));
                    *reinterpret_cast<uint32_t*>(g_c2 + off)       = pack_bf16x2(v0, v1);
                    *reinterpret_cast<uint32_t*>(g_c2 + XSZ + off) = pack_bf16x2(v0 - h0, v1 - h1);
                } else {
                    const float2 cv = *reinterpret_cast<const float2*>(g_cnn + off);
                    float2 o;
                    o.x = cv.x * (1.f / (1.f + __expf(-v0)));
                    o.y = cv.y * (1.f / (1.f + __expf(-v1)));
                    *reinterpret_cast<float2*>(out + off) = o;
                }
            }
        }
    }
}

// ------------------------------------------------------------------ launch
extern "C" void kernel_launch(void* const* d_in, const int* in_sizes, int n_in,
                              void* d_out, int out_size) {
    const float* x      = (const float*)d_in[0];
    const float* conv_w = (const float*)d_in[1];
    const float* conv_b = (const float*)d_in[2];
    const float* gate_w = (const float*)d_in[3];
    const float* gate_b = (const float*)d_in[4];
    float* out = (float*)d_out;

    cudaFuncSetAttribute(k_mma<48, true>,  cudaFuncAttributeMaxDynamicSharedMemorySize, SMEM_SZ);
    cudaFuncSetAttribute(k_mma<16, false>, cudaFuncAttributeMaxDynamicSharedMemorySize, SMEM_SZ);

    k_split_x<<<(int)(XSZ / 1024), 256>>>(x);
    k_split_convw<<<(int)(WSZ / 256), 256>>>(conv_w);
    k_split_gatew<<<(int)(GSZ / 1024), 256>>>(gate_w);

    dim3 grid(DDIM / 128, MTOT / 128);   // (8, 120)
    k_mma<48, true><<<grid, 256, SMEM_SZ>>>(conv_b, nullptr);
    k_mma<16, false><<<grid, 256, SMEM_SZ>>>(gate_b, out);
}

// round 4
// speedup vs baseline: 3.4201x; 1.5937x over previous
#include <cuda_runtime.h>
#include <cuda_fp16.h>
#include <cstdint>
#include <cstddef>

// Problem: B=16, T=960, D=1024, W=10
#define DDIM  1024
#define WWIN  10
#define MTOT  15360          // B*T
#define KCONV 3072           // 3*D

static constexpr size_t XSZ = (size_t)MTOT * DDIM;
static constexpr size_t WSZ = (size_t)DDIM * KCONV;
static constexpr size_t GSZ = (size_t)DDIM * DDIM;

// Device scratch (allocation-free rules)
__device__ float   g_cnn[XSZ];       // fp32 cnn
__device__ __half  g_x2[2 * XSZ];    // x   hi|lo fp16, [m][c]
__device__ __half  g_w1[WSZ];        // conv w fp16 (single plane), [n][k=s*1024+c]
__device__ __half  g_g1[GSZ];        // gate w fp16 (single plane), [e][d]
__device__ __half  g_c2[2 * XSZ];    // cnn hi|lo fp16, [m][d]

// ------------------------------------------------------------------ PTX helpers
__device__ __forceinline__ uint32_t smem_u32(const void* p) {
    uint32_t a;
    asm("{ .reg .u64 t; cvta.to.shared.u64 t, %1; cvt.u32.u64 %0, t; }" : "=r"(a) : "l"(p));
    return a;
}
__device__ __forceinline__ void cp16(uint32_t dst, const void* src, uint32_t sz) {
    asm volatile("cp.async.cg.shared.global [%0], [%1], 16, %2;"
                 :: "r"(dst), "l"(src), "r"(sz) : "memory");
}
__device__ __forceinline__ void cp_commit() {
    asm volatile("cp.async.commit_group;" ::: "memory");
}
template <int N>
__device__ __forceinline__ void cp_wait() {
    asm volatile("cp.async.wait_group %0;" :: "n"(N) : "memory");
}
__device__ __forceinline__ void ldsm4(uint32_t* r, uint32_t addr) {
    asm volatile("ldmatrix.sync.aligned.m8n8.x4.shared.b16 {%0,%1,%2,%3}, [%4];"
                 : "=r"(r[0]), "=r"(r[1]), "=r"(r[2]), "=r"(r[3]) : "r"(addr));
}
__device__ __forceinline__ void mma16816(float* d, const uint32_t* a, const uint32_t* b) {
    asm volatile("mma.sync.aligned.m16n8k16.row.col.f32.f16.f16.f32 "
                 "{%0,%1,%2,%3}, {%4,%5,%6,%7}, {%8,%9}, {%0,%1,%2,%3};"
                 : "+f"(d[0]), "+f"(d[1]), "+f"(d[2]), "+f"(d[3])
                 : "r"(a[0]), "r"(a[1]), "r"(a[2]), "r"(a[3]), "r"(b[0]), "r"(b[1]));
}
__device__ __forceinline__ uint32_t pack_h2(float a, float b) {
    return (uint32_t)__half_as_ushort(__float2half_rn(a)) |
           ((uint32_t)__half_as_ushort(__float2half_rn(b)) << 16);
}

// ------------------------------------------------------------------ preprocessing
__global__ void k_split_x(const float* __restrict__ x) {
    size_t i = ((size_t)blockIdx.x * 256 + threadIdx.x) * 4;
    float4 v = *reinterpret_cast<const float4*>(x + i);
    float vv[4] = {v.x, v.y, v.z, v.w};
    float hw[4];
#pragma unroll
    for (int j = 0; j < 4; ++j) hw[j] = __half2float(__float2half_rn(vv[j]));
    uint2 uh, ul;
    uh.x = pack_h2(vv[0], vv[1]); uh.y = pack_h2(vv[2], vv[3]);
    ul.x = pack_h2(vv[0] - hw[0], vv[1] - hw[1]);
    ul.y = pack_h2(vv[2] - hw[2], vv[3] - hw[3]);
    *reinterpret_cast<uint2*>(g_x2 + i)       = uh;
    *reinterpret_cast<uint2*>(g_x2 + XSZ + i) = ul;
}
__global__ void k_split_convw(const float* __restrict__ w) {
    size_t i = (size_t)blockIdx.x * 256 + threadIdx.x;   // over WSZ, out layout [n][s*1024+c]
    int n = (int)(i / KCONV);
    int k = (int)(i - (size_t)n * KCONV);
    int s = k >> 10, c = k & (DDIM - 1);
    g_w1[i] = __float2half_rn(w[(size_t)n * KCONV + c * 3 + s]);
}
__global__ void k_split_gatew(const float* __restrict__ gw) {
    size_t i = ((size_t)blockIdx.x * 256 + threadIdx.x) * 4;
    float4 v = *reinterpret_cast<const float4*>(gw + i);
    uint2 uh;
    uh.x = pack_h2(v.x, v.y); uh.y = pack_h2(v.z, v.w);
    *reinterpret_cast<uint2*>(g_g1 + i) = uh;
}

// ------------------------------------------------------------------ main GEMM
// CTA 128x128, BK=64 fp16, planes [Ah|Al|B] 16KB each, 2 buffers = 96KB.
// 8 warps in 4(M) x 2(N), warp tile 32x64. 2-pass split: acc += Ah*B + Al*B.
static constexpr int PL_AH = 0, PL_AL = 16384, PL_B = 32768;
static constexpr int BUFSZ = 49152;
static constexpr int SMEM_SZ = 2 * BUFSZ;   // 96 KB

template <int CHUNKS, bool IS_CONV>
__global__ __launch_bounds__(256, 2)
void k_mma(const float* __restrict__ bias, float* __restrict__ out) {
    extern __shared__ char smem[];
    const uint32_t sb = smem_u32(smem);

    const int tid = threadIdx.x;
    const int m0 = blockIdx.y * 128, n0 = blockIdx.x * 128;
    const int lane = tid & 31, w = tid >> 5;
    const int wm = w >> 1, wn = w & 1;          // warp grid 4(M) x 2(N)
    const int li = lane & 7, lg = lane >> 3;

    // loader geometry: thread -> (row lr, 4 of 8 16B sub-chunks)
    const int lr = tid >> 1;
    const int lh = (tid & 1) * 4;
    const int am = m0 + lr;
    const int amw = am % WWIN;
    const size_t ALO = XSZ;

    auto load_chunk = [&](int c, int buf) {
        const uint32_t base = sb + buf * BUFSZ;
        const __half* Ap;
        const __half* Bp;
        uint32_t asz = 16;
        if (IS_CONV) {
            const int s = c >> 4, dt = s - 1, kc = (c & 15) << 6;
            const bool valid = ((unsigned)(amw + dt)) < (unsigned)WWIN;
            asz = valid ? 16u : 0u;
            Ap = g_x2 + (size_t)(valid ? (am + dt) : am) * DDIM + kc;
            Bp = g_w1 + (size_t)(n0 + lr) * KCONV + (c << 6);
        } else {
            Ap = g_c2 + (size_t)am * DDIM + (c << 6);
            Bp = g_g1 + (size_t)(n0 + lr) * DDIM + (c << 6);
        }
#pragma unroll
        for (int j = 0; j < 4; ++j) {
            const int cc = lh + j;
            const uint32_t d = base + lr * 128 + ((cc ^ (lr & 7)) * 16);
            cp16(d + PL_AH, Ap + cc * 8, asz);
            cp16(d + PL_AL, Ap + ALO + cc * 8, asz);
            cp16(d + PL_B,  Bp + cc * 8, 16);
        }
    };

    float acc[2][8][4];
#pragma unroll
    for (int i = 0; i < 2; ++i)
#pragma unroll
        for (int j = 0; j < 8; ++j)
#pragma unroll
            for (int q = 0; q < 4; ++q) acc[i][j][q] = 0.f;

    load_chunk(0, 0);
    cp_commit();

    for (int it = 0; it < CHUNKS; ++it) {
        const int buf = it & 1;
        if (it + 1 < CHUNKS) { load_chunk(it + 1, buf ^ 1); cp_commit(); }
        if (it + 1 < CHUNKS) cp_wait<1>(); else cp_wait<0>();
        __syncthreads();

        const uint32_t bb = sb + buf * BUFSZ;
#pragma unroll
        for (int ks = 0; ks < 4; ++ks) {
            // B fragments: 4 x ldmatrix.x4 cover n64 x k16 (single plane)
            uint32_t Bf[4][4];
#pragma unroll
            for (int nt2 = 0; nt2 < 4; ++nt2) {
                const int br = wn * 64 + nt2 * 16 + li + (lg >> 1) * 8;
                const uint32_t cx = (uint32_t)((ks * 2 + (lg & 1)) ^ li);
                ldsm4(Bf[nt2], bb + PL_B + br * 128 + cx * 16);
            }
#pragma unroll
            for (int mt = 0; mt < 2; ++mt) {
                const int ar = wm * 32 + mt * 16 + li + (lg & 1) * 8;
                const uint32_t cx = (uint32_t)((ks * 2 + (lg >> 1)) ^ li);
                const uint32_t aa = bb + ar * 128 + cx * 16;
                uint32_t Ah[4], Al[4];
                ldsm4(Ah, aa + PL_AH);
                ldsm4(Al, aa + PL_AL);
#pragma unroll
                for (int nt = 0; nt < 8; ++nt) {
                    const uint32_t b2[2] = {Bf[nt >> 1][(nt & 1) * 2],
                                            Bf[nt >> 1][(nt & 1) * 2 + 1]};
                    mma16816(acc[mt][nt], Ah, b2);
                    mma16816(acc[mt][nt], Al, b2);
                }
            }
        }
        __syncthreads();
    }

    // ---- epilogue (direct from fragments)
#pragma unroll
    for (int mt = 0; mt < 2; ++mt) {
#pragma unroll
        for (int nt = 0; nt < 8; ++nt) {
            const int gn = n0 + wn * 64 + nt * 8 + (lane & 3) * 2;
            const float b0 = bias[gn], b1 = bias[gn + 1];
#pragma unroll
            for (int hh = 0; hh < 2; ++hh) {
                const int gm = m0 + wm * 32 + mt * 16 + (lane >> 2) + hh * 8;
                float v0 = acc[mt][nt][hh * 2 + 0] + b0;
                float v1 = acc[mt][nt][hh * 2 + 1] + b1;
                const size_t off = (size_t)gm * DDIM + gn;
                if (IS_CONV) {
                    *reinterpret_cast<float2*>(g_cnn + off) = make_float2(v0, v1);
                    const float h0 = __half2float(__float2half_rn(v0));
                    const float h1 = __half2float(__float2half_rn(v1));
                    *reinterpret_cast<uint32_t*>(g_c2 + off)       = pack_h2(v0, v1);
                    *reinterpret_cast<uint32_t*>(g_c2 + XSZ + off) = pack_h2(v0 - h0, v1 - h1);
                } else {
                    const float2 cv = *reinterpret_cast<const float2*>(g_cnn + off);
                    float2 o;
                    o.x = cv.x * (1.f / (1.f + __expf(-v0)));
                    o.y = cv.y * (1.f / (1.f + __expf(-v1)));
                    *reinterpret_cast<float2*>(out + off) = o;
                }
            }
        }
    }
}

// ------------------------------------------------------------------ launch
extern "C" void kernel_launch(void* const* d_in, const int* in_sizes, int n_in,
                              void* d_out, int out_size) {
    const float* x      = (const float*)d_in[0];
    const float* conv_w = (const float*)d_in[1];
    const float* conv_b = (const float*)d_in[2];
    const float* gate_w = (const float*)d_in[3];
    const float* gate_b = (const float*)d_in[4];
    float* out = (float*)d_out;

    cudaFuncSetAttribute(k_mma<48, true>,  cudaFuncAttributeMaxDynamicSharedMemorySize, SMEM_SZ);
    cudaFuncSetAttribute(k_mma<16, false>, cudaFuncAttributeMaxDynamicSharedMemorySize, SMEM_SZ);

    k_split_x<<<(int)(XSZ / 1024), 256>>>(x);
    k_split_convw<<<(int)(WSZ / 256), 256>>>(conv_w);
    k_split_gatew<<<(int)(GSZ / 1024), 256>>>(gate_w);

    dim3 grid(DDIM / 128, MTOT / 128);   // (8, 120)
    k_mma<48, true><<<grid, 256, SMEM_SZ>>>(conv_b, nullptr);
    k_mma<16, false><<<grid, 256, SMEM_SZ>>>(gate_b, out);
}

// round 5
// speedup vs baseline: 5.6539x; 1.6531x over previous
#include <cuda_runtime.h>
#include <cuda_fp16.h>
#include <cstdint>
#include <cstddef>

// Problem: B=16, T=960, D=1024, W=10
#define DDIM  1024
#define WWIN  10
#define MTOT  15360          // B*T
#define KCONV 3072           // 3*D

static constexpr size_t XSZ = (size_t)MTOT * DDIM;
static constexpr size_t WSZ = (size_t)DDIM * KCONV;
static constexpr size_t GSZ = (size_t)DDIM * DDIM;

// Device scratch (allocation-free rules)
__device__ float   g_cnn[XSZ];     // fp32 cnn
__device__ __half  g_x1[XSZ];      // x fp16, [m][c]
__device__ __half  g_w1[WSZ];      // conv w fp16, [n][k=s*1024+c]
__device__ __half  g_g1[GSZ];      // gate w fp16, [e][d]
__device__ __half  g_c1[XSZ];      // cnn fp16, [m][d]

// ------------------------------------------------------------------ PTX helpers
__device__ __forceinline__ uint32_t smem_u32(const void* p) {
    uint32_t a;
    asm("{ .reg .u64 t; cvta.to.shared.u64 t, %1; cvt.u32.u64 %0, t; }" : "=r"(a) : "l"(p));
    return a;
}
__device__ __forceinline__ void cp16(uint32_t dst, const void* src, uint32_t sz) {
    asm volatile("cp.async.cg.shared.global [%0], [%1], 16, %2;"
                 :: "r"(dst), "l"(src), "r"(sz) : "memory");
}
__device__ __forceinline__ void cp_commit() {
    asm volatile("cp.async.commit_group;" ::: "memory");
}
template <int N>
__device__ __forceinline__ void cp_wait() {
    asm volatile("cp.async.wait_group %0;" :: "n"(N) : "memory");
}
__device__ __forceinline__ void ldsm4(uint32_t* r, uint32_t addr) {
    asm volatile("ldmatrix.sync.aligned.m8n8.x4.shared.b16 {%0,%1,%2,%3}, [%4];"
                 : "=r"(r[0]), "=r"(r[1]), "=r"(r[2]), "=r"(r[3]) : "r"(addr));
}
__device__ __forceinline__ void mma16816(float* d, const uint32_t* a, const uint32_t* b) {
    asm volatile("mma.sync.aligned.m16n8k16.row.col.f32.f16.f16.f32 "
                 "{%0,%1,%2,%3}, {%4,%5,%6,%7}, {%8,%9}, {%0,%1,%2,%3};"
                 : "+f"(d[0]), "+f"(d[1]), "+f"(d[2]), "+f"(d[3])
                 : "r"(a[0]), "r"(a[1]), "r"(a[2]), "r"(a[3]), "r"(b[0]), "r"(b[1]));
}
__device__ __forceinline__ uint32_t pack_h2(float a, float b) {
    return (uint32_t)__half_as_ushort(__float2half_rn(a)) |
           ((uint32_t)__half_as_ushort(__float2half_rn(b)) << 16);
}

// ------------------------------------------------------------------ preprocessing
__global__ void k_split_x(const float* __restrict__ x) {
    size_t i = ((size_t)blockIdx.x * 256 + threadIdx.x) * 4;
    float4 v = *reinterpret_cast<const float4*>(x + i);
    uint2 uh;
    uh.x = pack_h2(v.x, v.y); uh.y = pack_h2(v.z, v.w);
    *reinterpret_cast<uint2*>(g_x1 + i) = uh;
}
__global__ void k_split_convw(const float* __restrict__ w) {
    size_t i = (size_t)blockIdx.x * 256 + threadIdx.x;   // over WSZ, out layout [n][s*1024+c]
    int n = (int)(i / KCONV);
    int k = (int)(i - (size_t)n * KCONV);
    int s = k >> 10, c = k & (DDIM - 1);
    g_w1[i] = __float2half_rn(w[(size_t)n * KCONV + c * 3 + s]);
}
__global__ void k_split_gatew(const float* __restrict__ gw) {
    size_t i = ((size_t)blockIdx.x * 256 + threadIdx.x) * 4;
    float4 v = *reinterpret_cast<const float4*>(gw + i);
    uint2 uh;
    uh.x = pack_h2(v.x, v.y); uh.y = pack_h2(v.z, v.w);
    *reinterpret_cast<uint2*>(g_g1 + i) = uh;
}

// ------------------------------------------------------------------ main GEMM
// CTA 128x128, BK=64 fp16. Stage: [A | B] 16KB planes = 32KB; 3-stage ring = 96KB.
// 8 warps in 4(M) x 2(N), warp tile 32x64, single-pass fp16 HMMA.
static constexpr int PL_A = 0, PL_B = 16384;
static constexpr int STSZ = 32768;
static constexpr int SMEM_SZ = 3 * STSZ;   // 96 KB

template <int CHUNKS, bool IS_CONV>
__global__ __launch_bounds__(256, 2)
void k_mma(const float* __restrict__ bias, float* __restrict__ out) {
    extern __shared__ char smem[];
    const uint32_t sb = smem_u32(smem);

    const int tid = threadIdx.x;
    const int m0 = blockIdx.y * 128, n0 = blockIdx.x * 128;
    const int lane = tid & 31, w = tid >> 5;
    const int wm = w >> 1, wn = w & 1;          // warp grid 4(M) x 2(N)
    const int li = lane & 7, lg = lane >> 3;

    // loader geometry: thread -> (row lr, 4 of 8 16B sub-chunks)
    const int lr = tid >> 1;
    const int lh = (tid & 1) * 4;
    const int am = m0 + lr;
    const int amw = am % WWIN;

    auto load_chunk = [&](int c, int stage) {
        const uint32_t base = sb + stage * STSZ;
        const __half* Ap;
        const __half* Bp;
        uint32_t asz = 16;
        if (IS_CONV) {
            const int s = c >> 4, dt = s - 1, kc = (c & 15) << 6;
            const bool valid = ((unsigned)(amw + dt)) < (unsigned)WWIN;
            asz = valid ? 16u : 0u;
            Ap = g_x1 + (size_t)(valid ? (am + dt) : am) * DDIM + kc;
            Bp = g_w1 + (size_t)(n0 + lr) * KCONV + (c << 6);
        } else {
            Ap = g_c1 + (size_t)am * DDIM + (c << 6);
            Bp = g_g1 + (size_t)(n0 + lr) * DDIM + (c << 6);
        }
#pragma unroll
        for (int j = 0; j < 4; ++j) {
            const int cc = lh + j;
            const uint32_t d = base + lr * 128 + ((cc ^ (lr & 7)) * 16);
            cp16(d + PL_A, Ap + cc * 8, asz);
            cp16(d + PL_B, Bp + cc * 8, 16);
        }
        cp_commit();
    };

    float acc[2][8][4];
#pragma unroll
    for (int i = 0; i < 2; ++i)
#pragma unroll
        for (int j = 0; j < 8; ++j)
#pragma unroll
            for (int q = 0; q < 4; ++q) acc[i][j][q] = 0.f;

    load_chunk(0, 0);
    if (CHUNKS > 1) load_chunk(1, 1);

    for (int it = 0; it < CHUNKS; ++it) {
        const int stage = it % 3;
        if (it + 1 < CHUNKS) cp_wait<1>(); else cp_wait<0>();
        __syncthreads();
        if (it + 2 < CHUNKS) load_chunk(it + 2, (it + 2) % 3);

        const uint32_t bb = sb + stage * STSZ;
#pragma unroll
        for (int ks = 0; ks < 4; ++ks) {
            uint32_t Bf[4][4];
#pragma unroll
            for (int nt2 = 0; nt2 < 4; ++nt2) {
                const int br = wn * 64 + nt2 * 16 + li + (lg >> 1) * 8;
                const uint32_t cx = (uint32_t)((ks * 2 + (lg & 1)) ^ li);
                ldsm4(Bf[nt2], bb + PL_B + br * 128 + cx * 16);
            }
#pragma unroll
            for (int mt = 0; mt < 2; ++mt) {
                const int ar = wm * 32 + mt * 16 + li + (lg & 1) * 8;
                const uint32_t cx = (uint32_t)((ks * 2 + (lg >> 1)) ^ li);
                uint32_t Af[4];
                ldsm4(Af, bb + PL_A + ar * 128 + cx * 16);
#pragma unroll
                for (int nt = 0; nt < 8; ++nt) {
                    const uint32_t b2[2] = {Bf[nt >> 1][(nt & 1) * 2],
                                            Bf[nt >> 1][(nt & 1) * 2 + 1]};
                    mma16816(acc[mt][nt], Af, b2);
                }
            }
        }
    }

    // ---- epilogue (direct from fragments)
#pragma unroll
    for (int mt = 0; mt < 2; ++mt) {
#pragma unroll
        for (int nt = 0; nt < 8; ++nt) {
            const int gn = n0 + wn * 64 + nt * 8 + (lane & 3) * 2;
            const float b0 = bias[gn], b1 = bias[gn + 1];
#pragma unroll
            for (int hh = 0; hh < 2; ++hh) {
                const int gm = m0 + wm * 32 + mt * 16 + (lane >> 2) + hh * 8;
                float v0 = acc[mt][nt][hh * 2 + 0] + b0;
                float v1 = acc[mt][nt][hh * 2 + 1] + b1;
                const size_t off = (size_t)gm * DDIM + gn;
                if (IS_CONV) {
                    *reinterpret_cast<float2*>(g_cnn + off) = make_float2(v0, v1);
                    *reinterpret_cast<uint32_t*>(g_c1 + off) = pack_h2(v0, v1);
                } else {
                    const float2 cv = *reinterpret_cast<const float2*>(g_cnn + off);
                    float2 o;
                    o.x = cv.x * (1.f / (1.f + __expf(-v0)));
                    o.y = cv.y * (1.f / (1.f + __expf(-v1)));
                    *reinterpret_cast<float2*>(out + off) = o;
                }
            }
        }
    }
}

// ------------------------------------------------------------------ launch
extern "C" void kernel_launch(void* const* d_in, const int* in_sizes, int n_in,
                              void* d_out, int out_size) {
    const float* x      = (const float*)d_in[0];
    const float* conv_w = (const float*)d_in[1];
    const float* conv_b = (const float*)d_in[2];
    const float* gate_w = (const float*)d_in[3];
    const float* gate_b = (const float*)d_in[4];
    float* out = (float*)d_out;

    cudaFuncSetAttribute(k_mma<48, true>,  cudaFuncAttributeMaxDynamicSharedMemorySize, SMEM_SZ);
    cudaFuncSetAttribute(k_mma<16, false>, cudaFuncAttributeMaxDynamicSharedMemorySize, SMEM_SZ);

    k_split_x<<<(int)(XSZ / 1024), 256>>>(x);
    k_split_convw<<<(int)(WSZ / 256), 256>>>(conv_w);
    k_split_gatew<<<(int)(GSZ / 1024), 256>>>(gate_w);

    dim3 grid(DDIM / 128, MTOT / 128);   // (8, 120)
    k_mma<48, true><<<grid, 256, SMEM_SZ>>>(conv_b, nullptr);
    k_mma<16, false><<<grid, 256, SMEM_SZ>>>(gate_b, out);
}